// round 1
// baseline (speedup 1.0000x reference)
#include <cuda_runtime.h>
#include <cstdint>

// ---------------------------------------------------------------------------
// InputStem: conv3d(1->16,s1) -> BN/ReLU -> conv3d(16->16,s1) -> BN/ReLU ->
//            conv3d(16->32,s2) -> BN/ReLU -> 16^3/stride-8 patches ->
//            GEMM (tok 128 + aux 32) -> LN(tokens) -> coords
// All fp32. BN stats via fp64 atomics. BN affine+ReLU fused into consumers.
// ---------------------------------------------------------------------------

#define VOL_FULL (128*128*128)      // 2,097,152
#define VOL_HALF (64*64*64)         // 262,144
#define N_PATCH  343                // 7*7*7
#define N_T      160                // 128 tok + 32 aux
#define PDIM     131072             // 32*16*16*16

// scratch (device globals — allocation-free rule)
__device__ float  g_buf1[2*16*VOL_FULL];   // conv1 raw out (256 MiB)
__device__ float  g_buf2[2*16*VOL_FULL];   // conv2 raw out (256 MiB)
__device__ float  g_buf3[2*32*VOL_HALF];   // conv3 raw out (64 MiB)
__device__ double g_red[3][64];            // per-stage: sum[0..C), sumsq[32..32+C)
__device__ float  g_sbt[3][64];            // per-stage: scale[0..C), bias[32..32+C)
__device__ float  g_gemm[2*N_PATCH*N_T];   // GEMM staging (pre-bias)

__device__ __forceinline__ float* bufptr(int sel) {
    return sel == 0 ? g_buf1 : (sel == 1 ? g_buf2 : g_buf3);
}

// ---------------------------------------------------------------------------
__global__ void k_zero() {
    int i = blockIdx.x * blockDim.x + threadIdx.x;
    if (i < 2*N_PATCH*N_T) g_gemm[i] = 0.f;
    if (i < 192) ((double*)g_red)[i] = 0.0;
}

// ---------------------------------------------------------------------------
// stride-1 3x3x3 conv. Block = one output row (b, z, y), 128 threads.
// Thread: 4 x-positions (tx, tx+32, tx+64, tx+96) x 4 out-channels.
// Input transform (BN affine + ReLU of previous stage) applied on smem fill.
// Writes RAW conv output.
template<int CI, int CO, bool APPLY>
__global__ void k_conv_s1(const float* __restrict__ in_ext,
                          const float* __restrict__ w,
                          int in_sel, int out_sel, int stage) {
    __shared__ float sm_in[9*130];
    __shared__ float sm_w[CO*27];
    const int y = blockIdx.x, z = blockIdx.y, b = blockIdx.z;
    const int tid = threadIdx.x;
    const int tx = tid & 31, cg = tid >> 5;

    const float* in = (in_sel < 0) ? in_ext : bufptr(in_sel);
    float* out = bufptr(out_sel);

    float acc[4][4];
#pragma unroll
    for (int j = 0; j < 4; j++)
#pragma unroll
        for (int v = 0; v < 4; v++) acc[j][v] = 0.f;

    for (int ci = 0; ci < CI; ci++) {
        float s_ = 1.f, t_ = 0.f;
        if (APPLY) { s_ = g_sbt[stage][ci]; t_ = g_sbt[stage][32+ci]; }

        for (int i = tid; i < CO*27; i += 128)
            sm_w[i] = w[((i/27)*CI + ci)*27 + (i%27)];

        const float* inc = in + (size_t)(b*CI + ci) * VOL_FULL;
        for (int i = tid; i < 9*130; i += 128) {
            int rr = i / 130, col = i % 130;
            int gz = z - 1 + rr/3, gy = y - 1 + rr%3, gx = col - 1;
            float v = 0.f;
            if (gz >= 0 && gz < 128 && gy >= 0 && gy < 128 && gx >= 0 && gx < 128) {
                v = inc[(gz*128 + gy)*128 + gx];
                if (APPLY) v = fmaxf(fmaf(v, s_, t_), 0.f);
            }
            sm_in[i] = v;
        }
        __syncthreads();

#pragma unroll
        for (int k = 0; k < 27; k++) {
            const int rr = k / 3, dx = k % 3;
            float iv[4];
#pragma unroll
            for (int v = 0; v < 4; v++)
                iv[v] = sm_in[rr*130 + tx + v*32 + dx];
#pragma unroll
            for (int j = 0; j < 4; j++) {
                float wv = sm_w[(cg*4 + j)*27 + k];
#pragma unroll
                for (int v = 0; v < 4; v++)
                    acc[j][v] = fmaf(iv[v], wv, acc[j][v]);
            }
        }
        __syncthreads();
    }

#pragma unroll
    for (int j = 0; j < 4; j++) {
        int co = cg*4 + j;
        float* oc = out + (((size_t)(b*CO + co)*128 + z)*128 + y)*128;
#pragma unroll
        for (int v = 0; v < 4; v++) oc[tx + v*32] = acc[j][v];
    }
}

// ---------------------------------------------------------------------------
// stride-2 3x3x3 conv, 16 -> 32 channels, in = g_buf2, out = g_buf3.
// Block = output row (b, zo, yo) of 64 voxels; 128 threads:
// thread = 2 x-positions (tx, tx+32) x 8 out-channels.
__global__ void k_conv_s2(const float* __restrict__ w, int stage) {
    __shared__ float sm_in[9*129];
    __shared__ float sm_w[32*27];
    const int y = blockIdx.x, z = blockIdx.y, b = blockIdx.z;
    const int tid = threadIdx.x;
    const int tx = tid & 31, cg = tid >> 5;

    float acc[8][2];
#pragma unroll
    for (int j = 0; j < 8; j++) { acc[j][0] = 0.f; acc[j][1] = 0.f; }

    for (int ci = 0; ci < 16; ci++) {
        const float s_ = g_sbt[stage][ci], t_ = g_sbt[stage][32+ci];
        for (int i = tid; i < 32*27; i += 128)
            sm_w[i] = w[((i/27)*16 + ci)*27 + (i%27)];

        const float* inc = g_buf2 + (size_t)(b*16 + ci) * VOL_FULL;
        for (int i = tid; i < 9*129; i += 128) {
            int rr = i / 129, col = i % 129;
            int gz = 2*z - 1 + rr/3, gy = 2*y - 1 + rr%3, gx = col - 1;
            float v = 0.f;
            if (gz >= 0 && gz < 128 && gy >= 0 && gy < 128 && gx >= 0 && gx < 128)
                v = fmaxf(fmaf(inc[(gz*128 + gy)*128 + gx], s_, t_), 0.f);
            sm_in[i] = v;
        }
        __syncthreads();

#pragma unroll
        for (int k = 0; k < 27; k++) {
            const int rr = k / 3, dx = k % 3;
            float iv0 = sm_in[rr*129 + 2*tx + dx];
            float iv1 = sm_in[rr*129 + 2*(tx+32) + dx];
#pragma unroll
            for (int j = 0; j < 8; j++) {
                float wv = sm_w[(cg*8 + j)*27 + k];
                acc[j][0] = fmaf(iv0, wv, acc[j][0]);
                acc[j][1] = fmaf(iv1, wv, acc[j][1]);
            }
        }
        __syncthreads();
    }

#pragma unroll
    for (int j = 0; j < 8; j++) {
        int co = cg*8 + j;
        size_t base = (((size_t)(b*32 + co)*64 + z)*64 + y)*64;
        g_buf3[base + tx]      = acc[j][0];
        g_buf3[base + tx + 32] = acc[j][1];
    }
}

// ---------------------------------------------------------------------------
// per-channel sum / sumsq of a RAW conv buffer (BN statistics)
__global__ void k_stats(int buf_sel, int stage, int C, int S) {
    const float* buf = bufptr(buf_sel);
    const int c = blockIdx.x, sl = blockIdx.y;
    const int chunk = S >> 6;   // 64 slices
    float s = 0.f, q = 0.f;
    for (int b = 0; b < 2; b++) {
        const float* p = buf + (size_t)(b*C + c)*S + (size_t)sl*chunk;
        for (int i = threadIdx.x; i < chunk; i += 256) {
            float v = p[i];
            s += v; q = fmaf(v, v, q);
        }
    }
#pragma unroll
    for (int o = 16; o; o >>= 1) {
        s += __shfl_down_sync(0xffffffffu, s, o);
        q += __shfl_down_sync(0xffffffffu, q, o);
    }
    __shared__ float ss[8], qq[8];
    int wp = threadIdx.x >> 5, ln = threadIdx.x & 31;
    if (ln == 0) { ss[wp] = s; qq[wp] = q; }
    __syncthreads();
    if (threadIdx.x == 0) {
        float S1 = 0.f, S2 = 0.f;
        for (int i = 0; i < 8; i++) { S1 += ss[i]; S2 += qq[i]; }
        atomicAdd(&g_red[stage][c],      (double)S1);
        atomicAdd(&g_red[stage][32 + c], (double)S2);
    }
}

__global__ void k_finalize(int stage, int C, float invN,
                           const float* __restrict__ g,
                           const float* __restrict__ b) {
    int c = threadIdx.x;
    if (c < C) {
        double mean = g_red[stage][c] * (double)invN;
        double var  = g_red[stage][32 + c] * (double)invN - mean*mean;
        float sc = g[c] * rsqrtf((float)var + 1e-5f);
        g_sbt[stage][c]      = sc;
        g_sbt[stage][32 + c] = b[c] - (float)mean * sc;
    }
}

// ---------------------------------------------------------------------------
// split-K patch GEMM. Block = (ci, pz, b): K-chunk = 16^3 of channel ci,
// M = 49 patches (py,px), N = 160 outputs. 160 threads, one t each,
// 49 register accumulators; partials via float atomics into g_gemm.
__global__ void k_gemm(const float* __restrict__ tok_w,
                       const float* __restrict__ aux_w) {
    __shared__ float sm_in[4096];       // one (ci, z) 64x64 plane, BN+ReLU applied
    __shared__ float sm_w[16*161];      // [dx][t] padded to kill bank conflicts
    const int ci = blockIdx.x, pz = blockIdx.y, b = blockIdx.z;
    const int t = threadIdx.x;          // 0..159
    const float s_ = g_sbt[2][ci], t_ = g_sbt[2][32 + ci];

    float acc[49];
#pragma unroll
    for (int p = 0; p < 49; p++) acc[p] = 0.f;

    for (int dz = 0; dz < 16; dz++) {
        const int z = 8*pz + dz;
        const float* pl = g_buf3 + ((size_t)(b*32 + ci)*64 + z)*4096;
        for (int i = t; i < 4096; i += 160)
            sm_in[i] = fmaxf(fmaf(pl[i], s_, t_), 0.f);
        __syncthreads();

        for (int dy = 0; dy < 16; dy++) {
            const int pbase = ((ci*16 + dz)*16 + dy)*16;
            for (int i = t; i < 2560; i += 160) {
                int tt = i >> 4, dx = i & 15;
                float wv = (tt < 128)
                    ? tok_w[(size_t)tt * PDIM + pbase + dx]
                    : aux_w[(size_t)(tt - 128) * PDIM + pbase + dx];
                sm_w[dx*161 + tt] = wv;
            }
            __syncthreads();

#pragma unroll
            for (int dx = 0; dx < 16; dx++) {
                float wv = sm_w[dx*161 + t];
#pragma unroll
                for (int py = 0; py < 7; py++) {
                    const int ro = (8*py + dy)*64 + dx;
#pragma unroll
                    for (int px = 0; px < 7; px++)
                        acc[py*7 + px] = fmaf(sm_in[ro + 8*px], wv, acc[py*7 + px]);
                }
            }
            __syncthreads();
        }
    }

    const int base = (b*N_PATCH + pz*49) * N_T + t;
#pragma unroll
    for (int p = 0; p < 49; p++)
        atomicAdd(&g_gemm[base + p*N_T], acc[p]);
}

// ---------------------------------------------------------------------------
// bias + LayerNorm(tokens) + aux bias + coords. Block per (b, n), 128 threads.
__global__ void k_final(const float* __restrict__ tok_b,
                        const float* __restrict__ aux_b,
                        const float* __restrict__ ln_g,
                        const float* __restrict__ ln_b,
                        float* __restrict__ out) {
    const int bn = blockIdx.x;           // b*343 + n
    const int n = bn % N_PATCH;
    const int t = threadIdx.x;           // 0..127

    float v = g_gemm[bn*N_T + t] + tok_b[t];
    float s = v, q = v*v;
#pragma unroll
    for (int o = 16; o; o >>= 1) {
        s += __shfl_down_sync(0xffffffffu, s, o);
        q += __shfl_down_sync(0xffffffffu, q, o);
    }
    __shared__ float ss[4], qq[4];
    int wp = t >> 5, ln = t & 31;
    if (ln == 0) { ss[wp] = s; qq[wp] = q; }
    __syncthreads();
    float S1 = ss[0] + ss[1] + ss[2] + ss[3];
    float S2 = qq[0] + qq[1] + qq[2] + qq[3];
    float mean = S1 * (1.f/128.f);
    float var  = S2 * (1.f/128.f) - mean*mean;
    float r = rsqrtf(var + 1e-5f);

    out[bn*128 + t] = (v - mean) * r * ln_g[t] + ln_b[t];

    if (t < 32)
        out[87808 + bn*32 + t] = g_gemm[bn*N_T + 128 + t] + aux_b[t];

    if (t < 3) {
        int pz = n / 49, py = (n / 7) % 7, px = n % 7;
        float c;
        if      (t == 0) c = ((float)pz * 8.f + 7.5f) * (1.f/63.f);
        else if (t == 1) c = ((float)py * 8.f + 7.5f) * (1.f/63.f);
        else             c = ((float)px * 8.f + 7.5f) * (1.f/63.f);
        out[109760 + bn*3 + t] = c;
    }
}

// ---------------------------------------------------------------------------
extern "C" void kernel_launch(void* const* d_in, const int* in_sizes, int n_in,
                              void* d_out, int out_size) {
    const float* x     = (const float*)d_in[0];
    const float* c1w   = (const float*)d_in[1];
    const float* bn1g  = (const float*)d_in[2];
    const float* bn1b  = (const float*)d_in[3];
    const float* c2w   = (const float*)d_in[4];
    const float* bn2g  = (const float*)d_in[5];
    const float* bn2b  = (const float*)d_in[6];
    const float* c3w   = (const float*)d_in[7];
    const float* bn3g  = (const float*)d_in[8];
    const float* bn3b  = (const float*)d_in[9];
    const float* tokw  = (const float*)d_in[10];
    const float* tokb  = (const float*)d_in[11];
    const float* auxw  = (const float*)d_in[12];
    const float* auxb  = (const float*)d_in[13];
    const float* lng   = (const float*)d_in[14];
    const float* lnb   = (const float*)d_in[15];
    float* out = (float*)d_out;

    k_zero<<<(2*N_PATCH*N_T + 255)/256, 256>>>();

    // conv1: x (1ch) -> buf1 raw
    k_conv_s1<1, 16, false><<<dim3(128,128,2), 128>>>(x, c1w, -1, 0, 0);
    k_stats<<<dim3(16,64), 256>>>(0, 0, 16, VOL_FULL);
    k_finalize<<<1, 32>>>(0, 16, 1.f/(2.f*VOL_FULL), bn1g, bn1b);

    // conv2: bn1(buf1) -> buf2 raw
    k_conv_s1<16, 16, true><<<dim3(128,128,2), 128>>>(nullptr, c2w, 0, 1, 0);
    k_stats<<<dim3(16,64), 256>>>(1, 1, 16, VOL_FULL);
    k_finalize<<<1, 32>>>(1, 16, 1.f/(2.f*VOL_FULL), bn2g, bn2b);

    // conv3 (stride 2): bn2(buf2) -> buf3 raw
    k_conv_s2<<<dim3(64,64,2), 128>>>(c3w, 1);
    k_stats<<<dim3(32,64), 256>>>(2, 2, 32, VOL_HALF);
    k_finalize<<<1, 32>>>(2, 32, 1.f/(2.f*VOL_HALF), bn3g, bn3b);

    // patch GEMM (split-K over channels) + epilogue
    k_gemm<<<dim3(32,7,2), 160>>>(tokw, auxw);
    k_final<<<686, 128>>>(tokb, auxb, lng, lnb, out);
}

// round 2
// speedup vs baseline: 1.2863x; 1.2863x over previous
#include <cuda_runtime.h>
#include <cstdint>

// ---------------------------------------------------------------------------
// InputStem R2: f32x2-packed FMA convs + LDS-lean register blocking,
// BN stats fused into conv kernels, L2-friendly split-K patch GEMM.
// ---------------------------------------------------------------------------

#define VOL_FULL (128*128*128)
#define VOL_HALF (64*64*64)
#define N_PATCH  343
#define N_T      160
#define PDIM     131072

typedef unsigned long long u64;

__device__ float  g_buf1[2*16*VOL_FULL];   // conv1 raw out
__device__ float  g_buf2[2*16*VOL_FULL];   // conv2 raw out
__device__ float  g_buf3[2*32*VOL_HALF];   // conv3 raw out
__device__ double g_redp[3][64][64];       // spread BN partials [stage][slot][c / 32+c]
__device__ float  g_sbt[3][64];            // BN scale[0..C) / bias[32..32+C)
__device__ float  g_gemm[2*N_PATCH*N_T];   // GEMM staging

__device__ __forceinline__ float* bufptr(int sel) {
    return sel == 0 ? g_buf1 : (sel == 1 ? g_buf2 : g_buf3);
}

// ---- f32x2 helpers ---------------------------------------------------------
__device__ __forceinline__ u64 pk2(float x, float y) {
    u64 r; asm("mov.b64 %0,{%1,%2};" : "=l"(r) : "f"(x), "f"(y)); return r;
}
__device__ __forceinline__ float2 upk(u64 v) {
    float2 r; asm("mov.b64 {%0,%1},%2;" : "=f"(r.x), "=f"(r.y) : "l"(v)); return r;
}
__device__ __forceinline__ void fma2(u64& d, u64 a, u64 b) {
    asm("fma.rn.f32x2 %0,%1,%2,%0;" : "+l"(d) : "l"(a), "l"(b));
}

// ---------------------------------------------------------------------------
__global__ void k_zero() {
    int i = blockIdx.x * blockDim.x + threadIdx.x;
    if (i < 2*N_PATCH*N_T) g_gemm[i] = 0.f;
    if (i < 3*64*64) ((double*)g_redp)[i] = 0.0;
}

// ---------------------------------------------------------------------------
// stride-1 3x3x3 conv, CI -> 16. Block = output row (b,z,y) of 128 x, 16 co.
// 128 thr: warp g owns co 4g..4g+3 (2 packed pairs), lane l owns x=4l..4l+3.
// Input row stored +1-shifted so aligned LDS.128 covers the halo.
// BN affine+ReLU of the previous stage applied on smem fill.
// Writes RAW output + fused per-channel sum/sumsq partials.
template<int CI, bool APPLY>
__global__ void __launch_bounds__(128) k_conv_s1(
    const float* __restrict__ in_ext, const float* __restrict__ w,
    int in_sel, int out_sel, int stage_in, int stage_out)
{
    __shared__ __align__(16) float sm_in[9*132];
    __shared__ float sm_w[CI*27*16];
    const int y = blockIdx.x, z = blockIdx.y, b = blockIdx.z;
    const int t = threadIdx.x, l = t & 31, g = t >> 5;
    const float* in = (in_sel < 0) ? in_ext : bufptr(in_sel);
    float* out = bufptr(out_sel);

    // preload ALL weights once: sm_w[(ci*27+k)*16 + co]
    for (int i = t; i < CI*27*16; i += 128) {
        int co = i & 15, r = i >> 4, k = r % 27, ci = r / 27;
        sm_w[i] = w[(co*CI + ci)*27 + k];
    }

    u64 acc[2][4];
#pragma unroll
    for (int j2 = 0; j2 < 2; j2++)
#pragma unroll
        for (int xx = 0; xx < 4; xx++) acc[j2][xx] = 0ULL;

    for (int ci = 0; ci < CI; ci++) {
        float s_ = 1.f, b_ = 0.f;
        if (APPLY) { s_ = g_sbt[stage_in][ci]; b_ = g_sbt[stage_in][32+ci]; }
        const float* inc = in + (size_t)(b*CI + ci) * VOL_FULL;
        for (int i = t; i < 1170; i += 128) {
            int rr = i / 130, idx = i - rr*130, c = idx - 1;
            int gz = z - 1 + rr/3, gy = y - 1 + rr%3;
            float v = 0.f;
            if ((unsigned)gz < 128u && (unsigned)gy < 128u && (unsigned)c < 128u) {
                v = inc[(gz*128 + gy)*128 + c];
                if (APPLY) v = fmaxf(fmaf(v, s_, b_), 0.f);
            }
            sm_in[rr*132 + idx] = v;
        }
        __syncthreads();

        const float* wci = sm_w + ci*432;
#pragma unroll
        for (int rr = 0; rr < 9; rr++) {
            float4 A = *(const float4*)(sm_in + rr*132 + 4*l);
            float4 B = *(const float4*)(sm_in + rr*132 + 4*l + 4);
            float a[7] = {A.x, A.y, A.z, A.w, B.x, B.y, B.z};
            u64 pv[7];
#pragma unroll
            for (int j = 0; j < 7; j++) pv[j] = pk2(a[j], a[j]);
#pragma unroll
            for (int dx = 0; dx < 3; dx++) {
                const int k = rr*3 + dx;
                u64 w0 = *(const u64*)(wci + k*16 + g*4);
                u64 w1 = *(const u64*)(wci + k*16 + g*4 + 2);
#pragma unroll
                for (int xx = 0; xx < 4; xx++) {
                    fma2(acc[0][xx], pv[dx+xx], w0);
                    fma2(acc[1][xx], pv[dx+xx], w1);
                }
            }
        }
        __syncthreads();
    }

    // unpack, store raw, fused stats
    float2 v[2][4];
#pragma unroll
    for (int j2 = 0; j2 < 2; j2++)
#pragma unroll
        for (int xx = 0; xx < 4; xx++) v[j2][xx] = upk(acc[j2][xx]);

#pragma unroll
    for (int j2 = 0; j2 < 2; j2++) {
        int co = g*4 + 2*j2;
        float4 lo = make_float4(v[j2][0].x, v[j2][1].x, v[j2][2].x, v[j2][3].x);
        float4 hi = make_float4(v[j2][0].y, v[j2][1].y, v[j2][2].y, v[j2][3].y);
        *(float4*)(out + (size_t)(b*16 + co)  *VOL_FULL + z*16384 + y*128 + 4*l) = lo;
        *(float4*)(out + (size_t)(b*16 + co+1)*VOL_FULL + z*16384 + y*128 + 4*l) = hi;
    }

    float s4[4], q4[4];
#pragma unroll
    for (int j2 = 0; j2 < 2; j2++) {
        float se = 0.f, qe = 0.f, so = 0.f, qo = 0.f;
#pragma unroll
        for (int xx = 0; xx < 4; xx++) {
            se += v[j2][xx].x; qe = fmaf(v[j2][xx].x, v[j2][xx].x, qe);
            so += v[j2][xx].y; qo = fmaf(v[j2][xx].y, v[j2][xx].y, qo);
        }
        s4[2*j2] = se; q4[2*j2] = qe; s4[2*j2+1] = so; q4[2*j2+1] = qo;
    }
#pragma unroll
    for (int c = 0; c < 4; c++) {
        float s = s4[c], q = q4[c];
#pragma unroll
        for (int o = 16; o; o >>= 1) {
            s += __shfl_down_sync(0xffffffffu, s, o);
            q += __shfl_down_sync(0xffffffffu, q, o);
        }
        if (l == 0) {
            atomicAdd(&g_redp[stage_out][z & 63][g*4 + c],      (double)s);
            atomicAdd(&g_redp[stage_out][z & 63][32 + g*4 + c], (double)q);
        }
    }
}

// ---------------------------------------------------------------------------
// stride-2 3x3x3 conv, 16 -> 32. Block = output row (b,z,y) of 64 x, 32 co.
// warp g owns co 8g..8g+7 (4 pairs), lane l owns x = 2l, 2l+1.
__global__ void __launch_bounds__(128) k_conv_s2(const float* __restrict__ w)
{
    __shared__ __align__(16) float sm_in[9*132];
    __shared__ float sm_w[27*32];
    const int y = blockIdx.x, z = blockIdx.y, b = blockIdx.z;
    const int t = threadIdx.x, l = t & 31, g = t >> 5;

    u64 acc[4][2];
#pragma unroll
    for (int j2 = 0; j2 < 4; j2++) { acc[j2][0] = 0ULL; acc[j2][1] = 0ULL; }

    for (int ci = 0; ci < 16; ci++) {
        const float s_ = g_sbt[1][ci], b_ = g_sbt[1][32+ci];
        for (int i = t; i < 864; i += 128) {
            int co = i & 31, k = i >> 5;
            sm_w[k*32 + co] = w[(co*16 + ci)*27 + k];
        }
        const float* inc = g_buf2 + (size_t)(b*16 + ci) * VOL_FULL;
        for (int i = t; i < 1170; i += 128) {
            int rr = i / 130, idx = i - rr*130, c = idx - 1;
            int gz = 2*z - 1 + rr/3, gy = 2*y - 1 + rr%3;
            float v = 0.f;
            if ((unsigned)gz < 128u && (unsigned)gy < 128u && (unsigned)c < 128u)
                v = fmaxf(fmaf(inc[(gz*128 + gy)*128 + c], s_, b_), 0.f);
            sm_in[rr*132 + idx] = v;
        }
        __syncthreads();

#pragma unroll
        for (int rr = 0; rr < 9; rr++) {
            float4 A = *(const float4*)(sm_in + rr*132 + 4*l);
            float a4 = sm_in[rr*132 + 4*l + 4];
            float a[5] = {A.x, A.y, A.z, A.w, a4};
            u64 pv[5];
#pragma unroll
            for (int j = 0; j < 5; j++) pv[j] = pk2(a[j], a[j]);
#pragma unroll
            for (int dx = 0; dx < 3; dx++) {
                const int k = rr*3 + dx;
#pragma unroll
                for (int j2 = 0; j2 < 4; j2++) {
                    u64 wv = *(const u64*)(sm_w + k*32 + g*8 + 2*j2);
                    fma2(acc[j2][0], pv[dx],   wv);
                    fma2(acc[j2][1], pv[dx+2], wv);
                }
            }
        }
        __syncthreads();
    }

    float2 v[4][2];
#pragma unroll
    for (int j2 = 0; j2 < 4; j2++) {
        v[j2][0] = upk(acc[j2][0]);
        v[j2][1] = upk(acc[j2][1]);
    }
#pragma unroll
    for (int j2 = 0; j2 < 4; j2++) {
        int co = g*8 + 2*j2;
        *(float2*)(g_buf3 + (size_t)(b*32 + co)  *VOL_HALF + z*4096 + y*64 + 2*l)
            = make_float2(v[j2][0].x, v[j2][1].x);
        *(float2*)(g_buf3 + (size_t)(b*32 + co+1)*VOL_HALF + z*4096 + y*64 + 2*l)
            = make_float2(v[j2][0].y, v[j2][1].y);
    }

    float s8[8], q8[8];
#pragma unroll
    for (int j2 = 0; j2 < 4; j2++) {
        s8[2*j2]   = v[j2][0].x + v[j2][1].x;
        q8[2*j2]   = fmaf(v[j2][0].x, v[j2][0].x, v[j2][1].x * v[j2][1].x);
        s8[2*j2+1] = v[j2][0].y + v[j2][1].y;
        q8[2*j2+1] = fmaf(v[j2][0].y, v[j2][0].y, v[j2][1].y * v[j2][1].y);
    }
#pragma unroll
    for (int c = 0; c < 8; c++) {
        float s = s8[c], q = q8[c];
#pragma unroll
        for (int o = 16; o; o >>= 1) {
            s += __shfl_down_sync(0xffffffffu, s, o);
            q += __shfl_down_sync(0xffffffffu, q, o);
        }
        if (l == 0) {
            atomicAdd(&g_redp[2][z & 63][g*8 + c],      (double)s);
            atomicAdd(&g_redp[2][z & 63][32 + g*8 + c], (double)q);
        }
    }
}

// ---------------------------------------------------------------------------
__global__ void k_finalize(int stage, int C, float invN,
                           const float* __restrict__ g,
                           const float* __restrict__ b)
{
    int c = threadIdx.x;
    if (c < C) {
        double s = 0.0, q = 0.0;
        for (int i = 0; i < 64; i++) {
            s += g_redp[stage][i][c];
            q += g_redp[stage][i][32 + c];
        }
        double mean = s * (double)invN;
        double var  = q * (double)invN - mean*mean;
        float sc = g[c] * rsqrtf((float)var + 1e-5f);
        g_sbt[stage][c]      = sc;
        g_sbt[stage][32 + c] = b[c] - (float)mean * sc;
    }
}

// ---------------------------------------------------------------------------
// split-K patch GEMM. Block (m = b*7+pz, ci). Plane relaid out in smem as
// [dy][dx][49 patches] (padded to 52) so inner operands are contiguous and
// load as LDS.128 pairs; accs packed f32x2 over patch pairs; w broadcast.
// Grid has ci slowest so the 14 same-ci blocks run together -> W slice L2-hot.
__global__ void __launch_bounds__(160) k_gemm(const float* __restrict__ tok_w,
                                              const float* __restrict__ aux_w)
{
    extern __shared__ __align__(16) float dsm[];
    float* in_s = dsm;           // 16*16*52 = 13312
    float* sw   = dsm + 13312;   // 16*161   = 2576
    const int m = blockIdx.x, ci = blockIdx.y;
    const int b = m / 7, pz = m - 7*b;
    const int t = threadIdx.x;
    const float s_ = g_sbt[2][ci], b_ = g_sbt[2][32 + ci];

    u64 acc[24];
#pragma unroll
    for (int k = 0; k < 24; k++) acc[k] = 0ULL;
    float acc48 = 0.f;

    for (int dz = 0; dz < 16; dz++) {
        const float* pl = g_buf3 + ((size_t)(b*32 + ci)*64 + 8*pz + dz)*4096;
        for (int i = t; i < 13312; i += 160) {
            int gi = i / 52, pp = i - gi*52;
            if (pp < 49) {
                int py = pp / 7, px = pp - py*7, dy = gi >> 4, dx = gi & 15;
                in_s[i] = fmaxf(fmaf(pl[(8*py + dy)*64 + 8*px + dx], s_, b_), 0.f);
            }
        }
        __syncthreads();

        for (int dy = 0; dy < 16; dy++) {
            const int pbase = ((ci*16 + dz)*16 + dy)*16;
            for (int i = t; i < 2560; i += 160) {
                int tt = i >> 4, dx = i & 15;
                sw[dx*161 + tt] = (tt < 128)
                    ? tok_w[(size_t)tt * PDIM + pbase + dx]
                    : aux_w[(size_t)(tt - 128) * PDIM + pbase + dx];
            }
            __syncthreads();

#pragma unroll 4
            for (int dx = 0; dx < 16; dx++) {
                float wv = sw[dx*161 + t];
                u64 wv2 = pk2(wv, wv);
                const ulonglong2* q2 = (const ulonglong2*)(in_s + (dy*16 + dx)*52);
#pragma unroll
                for (int k4 = 0; k4 < 12; k4++) {
                    ulonglong2 pr = q2[k4];
                    fma2(acc[2*k4],   pr.x, wv2);
                    fma2(acc[2*k4+1], pr.y, wv2);
                }
                acc48 = fmaf(in_s[(dy*16 + dx)*52 + 48], wv, acc48);
            }
            __syncthreads();
        }
    }

    const int gbase = (b*N_PATCH + pz*49)*N_T + t;
#pragma unroll
    for (int k = 0; k < 24; k++) {
        float2 u = upk(acc[k]);
        atomicAdd(&g_gemm[gbase + (2*k)  *N_T], u.x);
        atomicAdd(&g_gemm[gbase + (2*k+1)*N_T], u.y);
    }
    atomicAdd(&g_gemm[gbase + 48*N_T], acc48);
}

// ---------------------------------------------------------------------------
__global__ void k_final(const float* __restrict__ tok_b,
                        const float* __restrict__ aux_b,
                        const float* __restrict__ ln_g,
                        const float* __restrict__ ln_b,
                        float* __restrict__ out)
{
    const int bn = blockIdx.x;
    const int n = bn % N_PATCH;
    const int t = threadIdx.x;

    float v = g_gemm[bn*N_T + t] + tok_b[t];
    float s = v, q = v*v;
#pragma unroll
    for (int o = 16; o; o >>= 1) {
        s += __shfl_down_sync(0xffffffffu, s, o);
        q += __shfl_down_sync(0xffffffffu, q, o);
    }
    __shared__ float ss[4], qq[4];
    int wp = t >> 5, ln = t & 31;
    if (ln == 0) { ss[wp] = s; qq[wp] = q; }
    __syncthreads();
    float S1 = ss[0] + ss[1] + ss[2] + ss[3];
    float S2 = qq[0] + qq[1] + qq[2] + qq[3];
    float mean = S1 * (1.f/128.f);
    float var  = S2 * (1.f/128.f) - mean*mean;
    float r = rsqrtf(var + 1e-5f);

    out[bn*128 + t] = (v - mean) * r * ln_g[t] + ln_b[t];

    if (t < 32)
        out[87808 + bn*32 + t] = g_gemm[bn*N_T + 128 + t] + aux_b[t];

    if (t < 3) {
        int pz = n / 49, py = (n / 7) % 7, px = n % 7;
        float c;
        if      (t == 0) c = ((float)pz * 8.f + 7.5f) * (1.f/63.f);
        else if (t == 1) c = ((float)py * 8.f + 7.5f) * (1.f/63.f);
        else             c = ((float)px * 8.f + 7.5f) * (1.f/63.f);
        out[109760 + bn*3 + t] = c;
    }
}

// ---------------------------------------------------------------------------
extern "C" void kernel_launch(void* const* d_in, const int* in_sizes, int n_in,
                              void* d_out, int out_size) {
    const float* x     = (const float*)d_in[0];
    const float* c1w   = (const float*)d_in[1];
    const float* bn1g  = (const float*)d_in[2];
    const float* bn1b  = (const float*)d_in[3];
    const float* c2w   = (const float*)d_in[4];
    const float* bn2g  = (const float*)d_in[5];
    const float* bn2b  = (const float*)d_in[6];
    const float* c3w   = (const float*)d_in[7];
    const float* bn3g  = (const float*)d_in[8];
    const float* bn3b  = (const float*)d_in[9];
    const float* tokw  = (const float*)d_in[10];
    const float* tokb  = (const float*)d_in[11];
    const float* auxw  = (const float*)d_in[12];
    const float* auxb  = (const float*)d_in[13];
    const float* lng   = (const float*)d_in[14];
    const float* lnb   = (const float*)d_in[15];
    float* out = (float*)d_out;

    const int GEMM_SMEM = (16*16*52 + 16*161) * (int)sizeof(float); // 63552
    cudaFuncSetAttribute(k_gemm, cudaFuncAttributeMaxDynamicSharedMemorySize, GEMM_SMEM);

    k_zero<<<(2*N_PATCH*N_T + 255)/256, 256>>>();

    // conv1: x -> buf1 raw (+stats stage 0)
    k_conv_s1<1,  false><<<dim3(128,128,2), 128>>>(x, c1w, -1, 0, 0, 0);
    k_finalize<<<1, 32>>>(0, 16, 1.f/(2.f*VOL_FULL), bn1g, bn1b);

    // conv2: bn0(buf1) -> buf2 raw (+stats stage 1)
    k_conv_s1<16, true ><<<dim3(128,128,2), 128>>>(nullptr, c2w, 0, 1, 0, 1);
    k_finalize<<<1, 32>>>(1, 16, 1.f/(2.f*VOL_FULL), bn2g, bn2b);

    // conv3 (stride 2): bn1(buf2) -> buf3 raw (+stats stage 2)
    k_conv_s2<<<dim3(64,64,2), 128>>>(c3w);
    k_finalize<<<1, 32>>>(2, 32, 1.f/(2.f*VOL_HALF), bn3g, bn3b);

    // patch GEMM (same-ci blocks adjacent -> weight slice stays in L2)
    k_gemm<<<dim3(14,32), 160, GEMM_SMEM>>>(tokw, auxw);
    k_final<<<686, 128>>>(tokb, auxb, lng, lnb, out);
}

// round 3
// speedup vs baseline: 2.2245x; 1.7295x over previous
#include <cuda_runtime.h>
#include <cstdint>

// ---------------------------------------------------------------------------
// InputStem R3: hoisted fill addressing, 2-row blocks, f32x2 FMA convs,
// broadcast-tiled GEMM (2t per thread), fused BN stats.
// ---------------------------------------------------------------------------

#define VOL_FULL (128*128*128)
#define VOL_HALF (64*64*64)
#define N_PATCH  343
#define N_T      160
#define PDIM     131072

typedef unsigned long long u64;

__device__ float  g_buf1[2*16*VOL_FULL];
__device__ float  g_buf2[2*16*VOL_FULL];
__device__ float  g_buf3[2*32*VOL_HALF];
__device__ double g_redp[3][64][64];
__device__ float  g_sbt[3][64];
__device__ float  g_gemm[2*N_PATCH*N_T];

__device__ __forceinline__ float* bufptr(int sel) {
    return sel == 0 ? g_buf1 : (sel == 1 ? g_buf2 : g_buf3);
}

__device__ __forceinline__ u64 pk2(float x, float y) {
    u64 r; asm("mov.b64 %0,{%1,%2};" : "=l"(r) : "f"(x), "f"(y)); return r;
}
__device__ __forceinline__ float2 upk(u64 v) {
    float2 r; asm("mov.b64 {%0,%1},%2;" : "=f"(r.x), "=f"(r.y) : "l"(v)); return r;
}
__device__ __forceinline__ void fma2(u64& d, u64 a, u64 b) {
    asm("fma.rn.f32x2 %0,%1,%2,%0;" : "+l"(d) : "l"(a), "l"(b));
}

// ---------------------------------------------------------------------------
__global__ void k_zero() {
    int i = blockIdx.x * blockDim.x + threadIdx.x;
    if (i < 2*N_PATCH*N_T) g_gemm[i] = 0.f;
    if (i < 3*64*64) ((double*)g_redp)[i] = 0.0;
}

// ---------------------------------------------------------------------------
// stride-1 3x3x3 conv, CI -> 16. Block = TWO output y-rows (b, z, y0..y0+1),
// 128 thr: warp g owns co 4g..4g+3 (2 f32x2 pairs), lane l owns x 4l..4l+3.
// Fill addressing hoisted out of the ci loop into gOff[13].
template<int CI, bool APPLY>
__global__ void __launch_bounds__(128) k_conv_s1(
    const float* __restrict__ in_ext, const float* __restrict__ w,
    int in_sel, int out_sel, int stage_in, int stage_out)
{
    __shared__ __align__(16) float sm_in[13*128];   // 12 rows x 132 = 1584 used
    __shared__ float sm_w[CI*27*16];
    const int y0 = 2*blockIdx.x, z = blockIdx.y, b = blockIdx.z;
    const int t = threadIdx.x, l = t & 31, g = t >> 5;
    const float* in = (in_sel < 0) ? in_ext : bufptr(in_sel);
    float* out = bufptr(out_sel);

    for (int i = t; i < CI*27*16; i += 128) {
        int co = i & 15, r = i >> 4, k = r % 27, ci = r / 27;
        sm_w[i] = w[(co*CI + ci)*27 + k];
    }

    // hoisted fill offsets: 12 input rows (3 gz x 4 gy) x 132 (x -1..130)
    int gOff[13];
#pragma unroll
    for (int j = 0; j < 13; j++) {
        int i = t + 128*j, off = -1;
        if (i < 1584) {
            int r = i / 132, idx = i - 132*r;
            int gz = z - 1 + (r >> 2), gy = y0 - 1 + (r & 3), gx = idx - 1;
            if ((unsigned)gz < 128u && (unsigned)gy < 128u && (unsigned)gx < 128u)
                off = (gz*128 + gy)*128 + gx;
        }
        gOff[j] = off;
    }

    u64 acc[2][2][4];
#pragma unroll
    for (int yr = 0; yr < 2; yr++)
#pragma unroll
        for (int j2 = 0; j2 < 2; j2++)
#pragma unroll
            for (int xx = 0; xx < 4; xx++) acc[yr][j2][xx] = 0ULL;

    for (int ci = 0; ci < CI; ci++) {
        float s_ = 1.f, b_ = 0.f;
        if (APPLY) { s_ = g_sbt[stage_in][ci]; b_ = g_sbt[stage_in][32+ci]; }
        const float* inc = in + (size_t)(b*CI + ci) * VOL_FULL;
        __syncthreads();
#pragma unroll
        for (int j = 0; j < 13; j++) {
            int off = gOff[j];
            float v = 0.f;
            if (off >= 0) {
                v = inc[off];
                if (APPLY) v = fmaxf(fmaf(v, s_, b_), 0.f);
            }
            sm_in[t + 128*j] = v;
        }
        __syncthreads();

        const float* wci = sm_w + ci*432;
#pragma unroll
        for (int r = 0; r < 12; r++) {
            float4 A = *(const float4*)(sm_in + r*132 + 4*l);
            float4 B = *(const float4*)(sm_in + r*132 + 4*l + 4);
            float a[7] = {A.x, A.y, A.z, A.w, B.x, B.y, B.z};
            u64 pv[7];
#pragma unroll
            for (int j = 0; j < 7; j++) pv[j] = pk2(a[j], a[j]);
            const int dz = r >> 2, m = r & 3;
#pragma unroll
            for (int yr = 0; yr < 2; yr++) {
                const int dyy = m - yr;
                if (dyy < 0 || dyy > 2) continue;       // compile-time
                const int kb = dz*9 + dyy*3;
#pragma unroll
                for (int dx = 0; dx < 3; dx++) {
                    u64 w0 = *(const u64*)(wci + (kb+dx)*16 + g*4);
                    u64 w1 = *(const u64*)(wci + (kb+dx)*16 + g*4 + 2);
#pragma unroll
                    for (int xx = 0; xx < 4; xx++) {
                        fma2(acc[yr][0][xx], pv[dx+xx], w0);
                        fma2(acc[yr][1][xx], pv[dx+xx], w1);
                    }
                }
            }
        }
    }

    float2 v[2][2][4];
#pragma unroll
    for (int yr = 0; yr < 2; yr++)
#pragma unroll
        for (int j2 = 0; j2 < 2; j2++)
#pragma unroll
            for (int xx = 0; xx < 4; xx++) v[yr][j2][xx] = upk(acc[yr][j2][xx]);

#pragma unroll
    for (int yr = 0; yr < 2; yr++)
#pragma unroll
        for (int j2 = 0; j2 < 2; j2++) {
            int co = g*4 + 2*j2;
            float4 lo = make_float4(v[yr][j2][0].x, v[yr][j2][1].x, v[yr][j2][2].x, v[yr][j2][3].x);
            float4 hi = make_float4(v[yr][j2][0].y, v[yr][j2][1].y, v[yr][j2][2].y, v[yr][j2][3].y);
            size_t base = (size_t)(b*16 + co)*VOL_FULL + z*16384 + (y0+yr)*128 + 4*l;
            *(float4*)(out + base) = lo;
            *(float4*)(out + base + VOL_FULL) = hi;
        }

#pragma unroll
    for (int c = 0; c < 4; c++) {
        float s = 0.f, q = 0.f;
#pragma unroll
        for (int yr = 0; yr < 2; yr++)
#pragma unroll
            for (int xx = 0; xx < 4; xx++) {
                float val = (c & 1) ? v[yr][c>>1][xx].y : v[yr][c>>1][xx].x;
                s += val; q = fmaf(val, val, q);
            }
#pragma unroll
        for (int o = 16; o; o >>= 1) {
            s += __shfl_down_sync(0xffffffffu, s, o);
            q += __shfl_down_sync(0xffffffffu, q, o);
        }
        if (l == 0) {
            atomicAdd(&g_redp[stage_out][z & 63][g*4 + c],      (double)s);
            atomicAdd(&g_redp[stage_out][z & 63][32 + g*4 + c], (double)q);
        }
    }
}

// ---------------------------------------------------------------------------
// stride-2 3x3x3 conv, 16 -> 32. Block = TWO output y-rows (b, z, 2bx..2bx+1),
// warp g owns co 8g..8g+7 (4 pairs), lane l owns out x = 2l, 2l+1.
__global__ void __launch_bounds__(128) k_conv_s2(const float* __restrict__ w)
{
    __shared__ __align__(16) float sm_in[16*128];   // 15 rows x 132 = 1980 used
    __shared__ float sm_w[27*32];
    const int bx = blockIdx.x, z = blockIdx.y, b = blockIdx.z;
    const int t = threadIdx.x, l = t & 31, g = t >> 5;

    // 15 input rows: gz = 2z-1+dzr (dzr 0..2), gy = 4bx-1+m (m 0..4)
    int gOff[16];
#pragma unroll
    for (int j = 0; j < 16; j++) {
        int i = t + 128*j, off = -1;
        if (i < 1980) {
            int r = i / 132, idx = i - 132*r;
            int dzr = r / 5, m = r - 5*dzr;
            int gz = 2*z - 1 + dzr, gy = 4*bx - 1 + m, gx = idx - 1;
            if ((unsigned)gz < 128u && (unsigned)gy < 128u && (unsigned)gx < 128u)
                off = (gz*128 + gy)*128 + gx;
        }
        gOff[j] = off;
    }

    u64 acc[2][4][2];
#pragma unroll
    for (int yr = 0; yr < 2; yr++)
#pragma unroll
        for (int j2 = 0; j2 < 4; j2++) { acc[yr][j2][0] = 0ULL; acc[yr][j2][1] = 0ULL; }

    for (int ci = 0; ci < 16; ci++) {
        const float s_ = g_sbt[1][ci], b_ = g_sbt[1][32+ci];
        __syncthreads();
        for (int i = t; i < 864; i += 128) {
            int co = i & 31, k = i >> 5;
            sm_w[k*32 + co] = w[(co*16 + ci)*27 + k];
        }
        const float* inc = g_buf2 + (size_t)(b*16 + ci) * VOL_FULL;
#pragma unroll
        for (int j = 0; j < 16; j++) {
            int off = gOff[j];
            float v = 0.f;
            if (off >= 0)
                v = fmaxf(fmaf(inc[off], s_, b_), 0.f);
            sm_in[t + 128*j] = v;
        }
        __syncthreads();

#pragma unroll
        for (int r = 0; r < 15; r++) {
            float4 A = *(const float4*)(sm_in + r*132 + 4*l);
            float a4 = sm_in[r*132 + 4*l + 4];
            float a[5] = {A.x, A.y, A.z, A.w, a4};
            u64 pv[5];
#pragma unroll
            for (int j = 0; j < 5; j++) pv[j] = pk2(a[j], a[j]);
            const int dzr = r / 5, m = r - 5*dzr;
#pragma unroll
            for (int yr = 0; yr < 2; yr++) {
                const int dyy = m - 2*yr;
                if (dyy < 0 || dyy > 2) continue;       // compile-time
                const int kb = dzr*9 + dyy*3;
#pragma unroll
                for (int dx = 0; dx < 3; dx++) {
#pragma unroll
                    for (int j2 = 0; j2 < 4; j2++) {
                        u64 wv = *(const u64*)(sm_w + (kb+dx)*32 + g*8 + 2*j2);
                        fma2(acc[yr][j2][0], pv[dx],   wv);
                        fma2(acc[yr][j2][1], pv[dx+2], wv);
                    }
                }
            }
        }
    }

    float2 v[2][4][2];
#pragma unroll
    for (int yr = 0; yr < 2; yr++)
#pragma unroll
        for (int j2 = 0; j2 < 4; j2++) {
            v[yr][j2][0] = upk(acc[yr][j2][0]);
            v[yr][j2][1] = upk(acc[yr][j2][1]);
        }

#pragma unroll
    for (int yr = 0; yr < 2; yr++)
#pragma unroll
        for (int j2 = 0; j2 < 4; j2++) {
            int co = g*8 + 2*j2;
            size_t base = (size_t)(b*32 + co)*VOL_HALF + z*4096 + (2*bx+yr)*64 + 2*l;
            *(float2*)(g_buf3 + base) = make_float2(v[yr][j2][0].x, v[yr][j2][1].x);
            *(float2*)(g_buf3 + base + VOL_HALF) = make_float2(v[yr][j2][0].y, v[yr][j2][1].y);
        }

#pragma unroll
    for (int c = 0; c < 8; c++) {
        float s = 0.f, q = 0.f;
#pragma unroll
        for (int yr = 0; yr < 2; yr++)
#pragma unroll
            for (int xx = 0; xx < 2; xx++) {
                float val = (c & 1) ? v[yr][c>>1][xx].y : v[yr][c>>1][xx].x;
                s += val; q = fmaf(val, val, q);
            }
#pragma unroll
        for (int o = 16; o; o >>= 1) {
            s += __shfl_down_sync(0xffffffffu, s, o);
            q += __shfl_down_sync(0xffffffffu, q, o);
        }
        if (l == 0) {
            atomicAdd(&g_redp[2][z & 63][g*8 + c],      (double)s);
            atomicAdd(&g_redp[2][z & 63][32 + g*8 + c], (double)q);
        }
    }
}

// ---------------------------------------------------------------------------
__global__ void k_finalize(int stage, int C, float invN,
                           const float* __restrict__ g,
                           const float* __restrict__ b)
{
    int c = threadIdx.x;
    if (c < C) {
        double s = 0.0, q = 0.0;
        for (int i = 0; i < 64; i++) {
            s += g_redp[stage][i][c];
            q += g_redp[stage][i][32 + c];
        }
        double mean = s * (double)invN;
        double var  = q * (double)invN - mean*mean;
        float sc = g[c] * rsqrtf((float)var + 1e-5f);
        g_sbt[stage][c]      = sc;
        g_sbt[stage][32 + c] = b[c] - (float)mean * sc;
    }
}

// ---------------------------------------------------------------------------
// split-K patch GEMM. Block (m=b*7+pz, ci). Plane relaid as [dy][dx][64pad]:
// patch-pair loads are warp-uniform broadcasts; thread owns t-values tg & tg+80
// and half the patches -> LDS traffic ~2x lower, weight reads stride-1.
__global__ void __launch_bounds__(160) k_gemm(const float* __restrict__ tok_w,
                                              const float* __restrict__ aux_w)
{
    extern __shared__ __align__(16) float dsm[];
    float* in_s = dsm;            // 16*16*64 = 16384
    float* sw   = dsm + 16384;    // 16*160   = 2560
    const int m = blockIdx.x, ci = blockIdx.y;
    const int b = m / 7, pz = m - 7*b;
    const int tid = threadIdx.x;
    const int h = (tid >= 80) ? 1 : 0, tg = tid - 80*h;
    const float s_ = g_sbt[2][ci], b_ = g_sbt[2][32 + ci];

    u64 acc[2][12];
#pragma unroll
    for (int ti = 0; ti < 2; ti++)
#pragma unroll
        for (int k = 0; k < 12; k++) acc[ti][k] = 0ULL;
    float accs[2] = {0.f, 0.f};

    for (int dz = 0; dz < 16; dz++) {
        const float* pl = g_buf3 + ((size_t)(b*32 + ci)*64 + 8*pz + dz)*4096;
        __syncthreads();
        for (int i = tid; i < 16384; i += 160) {
            int gi = i >> 6, pp = i & 63;
            float v = 0.f;
            if (pp < 49) {
                int py = pp / 7, px = pp - 7*py;
                int dy = gi >> 4, dx = gi & 15;
                v = fmaxf(fmaf(pl[(8*py + dy)*64 + 8*px + dx], s_, b_), 0.f);
            }
            in_s[i] = v;
        }
        __syncthreads();

        for (int dy = 0; dy < 16; dy++) {
            // weights for (ci,dz,dy): sw[dx*160 + t], 16 consecutive floats/thread
            const int pbase = ((ci*16 + dz)*16 + dy)*16;
            {
                const float* wrow = (tid < 128)
                    ? tok_w + (size_t)tid * PDIM + pbase
                    : aux_w + (size_t)(tid - 128) * PDIM + pbase;
                float4 w0 = *(const float4*)(wrow);
                float4 w1 = *(const float4*)(wrow + 4);
                float4 w2 = *(const float4*)(wrow + 8);
                float4 w3 = *(const float4*)(wrow + 12);
                float wv[16] = {w0.x,w0.y,w0.z,w0.w, w1.x,w1.y,w1.z,w1.w,
                                w2.x,w2.y,w2.z,w2.w, w3.x,w3.y,w3.z,w3.w};
#pragma unroll
                for (int dx = 0; dx < 16; dx++) sw[dx*160 + tid] = wv[dx];
            }
            __syncthreads();

#pragma unroll 4
            for (int dx = 0; dx < 16; dx++) {
                float w0 = sw[dx*160 + tg];
                float w1 = sw[dx*160 + tg + 80];
                u64 w0p = pk2(w0, w0), w1p = pk2(w1, w1);
                const float* row = in_s + (dy*16 + dx)*64 + h*24;
                const ulonglong2* q = (const ulonglong2*)row;
#pragma unroll
                for (int k3 = 0; k3 < 6; k3++) {
                    ulonglong2 pr = q[k3];
                    fma2(acc[0][2*k3],   pr.x, w0p);
                    fma2(acc[0][2*k3+1], pr.y, w0p);
                    fma2(acc[1][2*k3],   pr.x, w1p);
                    fma2(acc[1][2*k3+1], pr.y, w1p);
                }
                if (h) {
                    float a48 = row[24];
                    accs[0] = fmaf(a48, w0, accs[0]);
                    accs[1] = fmaf(a48, w1, accs[1]);
                }
            }
            __syncthreads();
        }
    }

    const int gbase = (b*N_PATCH + pz*49)*N_T;
#pragma unroll
    for (int ti = 0; ti < 2; ti++) {
        int tt = tg + 80*ti;
#pragma unroll
        for (int k = 0; k < 12; k++) {
            float2 u = upk(acc[ti][k]);
            int p = h*24 + 2*k;
            atomicAdd(&g_gemm[gbase + p*N_T + tt],     u.x);
            atomicAdd(&g_gemm[gbase + (p+1)*N_T + tt], u.y);
        }
        if (h) atomicAdd(&g_gemm[gbase + 48*N_T + tt], accs[ti]);
    }
}

// ---------------------------------------------------------------------------
__global__ void k_final(const float* __restrict__ tok_b,
                        const float* __restrict__ aux_b,
                        const float* __restrict__ ln_g,
                        const float* __restrict__ ln_b,
                        float* __restrict__ out)
{
    const int bn = blockIdx.x;
    const int n = bn % N_PATCH;
    const int t = threadIdx.x;

    float v = g_gemm[bn*N_T + t] + tok_b[t];
    float s = v, q = v*v;
#pragma unroll
    for (int o = 16; o; o >>= 1) {
        s += __shfl_down_sync(0xffffffffu, s, o);
        q += __shfl_down_sync(0xffffffffu, q, o);
    }
    __shared__ float ss[4], qq[4];
    int wp = t >> 5, ln = t & 31;
    if (ln == 0) { ss[wp] = s; qq[wp] = q; }
    __syncthreads();
    float S1 = ss[0] + ss[1] + ss[2] + ss[3];
    float S2 = qq[0] + qq[1] + qq[2] + qq[3];
    float mean = S1 * (1.f/128.f);
    float var  = S2 * (1.f/128.f) - mean*mean;
    float r = rsqrtf(var + 1e-5f);

    out[bn*128 + t] = (v - mean) * r * ln_g[t] + ln_b[t];

    if (t < 32)
        out[87808 + bn*32 + t] = g_gemm[bn*N_T + 128 + t] + aux_b[t];

    if (t < 3) {
        int pz = n / 49, py = (n / 7) % 7, px = n % 7;
        float c;
        if      (t == 0) c = ((float)pz * 8.f + 7.5f) * (1.f/63.f);
        else if (t == 1) c = ((float)py * 8.f + 7.5f) * (1.f/63.f);
        else             c = ((float)px * 8.f + 7.5f) * (1.f/63.f);
        out[109760 + bn*3 + t] = c;
    }
}

// ---------------------------------------------------------------------------
extern "C" void kernel_launch(void* const* d_in, const int* in_sizes, int n_in,
                              void* d_out, int out_size) {
    const float* x     = (const float*)d_in[0];
    const float* c1w   = (const float*)d_in[1];
    const float* bn1g  = (const float*)d_in[2];
    const float* bn1b  = (const float*)d_in[3];
    const float* c2w   = (const float*)d_in[4];
    const float* bn2g  = (const float*)d_in[5];
    const float* bn2b  = (const float*)d_in[6];
    const float* c3w   = (const float*)d_in[7];
    const float* bn3g  = (const float*)d_in[8];
    const float* bn3b  = (const float*)d_in[9];
    const float* tokw  = (const float*)d_in[10];
    const float* tokb  = (const float*)d_in[11];
    const float* auxw  = (const float*)d_in[12];
    const float* auxb  = (const float*)d_in[13];
    const float* lng   = (const float*)d_in[14];
    const float* lnb   = (const float*)d_in[15];
    float* out = (float*)d_out;

    const int GEMM_SMEM = (16384 + 2560) * (int)sizeof(float);   // 75776
    cudaFuncSetAttribute(k_gemm, cudaFuncAttributeMaxDynamicSharedMemorySize, GEMM_SMEM);

    k_zero<<<(2*N_PATCH*N_T + 255)/256, 256>>>();

    // conv1: x -> buf1 raw (+stats stage 0)
    k_conv_s1<1,  false><<<dim3(64,128,2), 128>>>(x, c1w, -1, 0, 0, 0);
    k_finalize<<<1, 32>>>(0, 16, 1.f/(2.f*VOL_FULL), bn1g, bn1b);

    // conv2: bn0(buf1) -> buf2 raw (+stats stage 1)
    k_conv_s1<16, true ><<<dim3(64,128,2), 128>>>(nullptr, c2w, 0, 1, 0, 1);
    k_finalize<<<1, 32>>>(1, 16, 1.f/(2.f*VOL_FULL), bn2g, bn2b);

    // conv3 (stride 2): bn1(buf2) -> buf3 raw (+stats stage 2)
    k_conv_s2<<<dim3(32,64,2), 128>>>(c3w);
    k_finalize<<<1, 32>>>(2, 32, 1.f/(2.f*VOL_HALF), bn3g, bn3b);

    // patch GEMM + epilogue
    k_gemm<<<dim3(14,32), 160, GEMM_SMEM>>>(tokw, auxw);
    k_final<<<686, 128>>>(tokb, auxb, lng, lnb, out);
}